// round 5
// baseline (speedup 1.0000x reference)
#include <cuda_runtime.h>

// Geometry: (1, D=24, H=24, W=16, C=2); N = 9216 voxels.
#define NV   9216
#define NB   144     // blocks; <= 148 SMs so all co-resident (safe grid barrier)
#define NT   384
#define NGRP 12      // two-level barrier: 12 groups of 12 blocks

// Taylor rank-5 factorization of the bilateral intensity kernel:
//   exp(-(Ii-Ij)^2/18) = e^{-Ii^2/18} e^{-Ij^2/18} * sum_k c_k Ii^k Ij^k,
//   c_k = (1/9)^k / k!,  truncation error ~1.4e-7.
// Basis fields f = 2k+c (k=0..4, c=0..1); spatial fields f = 10+c.

__device__ float g_xy[18][NV];    // xy-blurred fields (12..17 = norm, iter 1 only)
__device__ float g_zb[12][NV];    // z-blurred basis fields
__device__ float g_nrm[6][NV];    // z-blurred norm fields (0..4 bilateral basis, 5 spatial)
__device__ int   g_gcnt[NGRP][64];  // group arrival counters (monotonic), 256B apart
__device__ int   g_gep [NGRP][64];  // group epochs
__device__ int   g_rcnt;            // root counter (monotonic)
__device__ int   g_rep;             // root epoch

__device__ __forceinline__ int ld_acq(const int* p) {
    int v; asm volatile("ld.global.acquire.gpu.b32 %0, [%1];" : "=r"(v) : "l"(p) : "memory");
    return v;
}
__device__ __forceinline__ void st_rel(int* p, int v) {
    asm volatile("st.global.release.gpu.b32 [%0], %1;" :: "l"(p), "r"(v) : "memory");
}

// Two-level grid barrier. Counters are monotonic (exactly NGRP increments per
// counter per barrier), so no resets are needed and state is replay-safe.
__device__ __forceinline__ void gridbar(int& target, int b) {
    __syncthreads();
    if (threadIdx.x == 0) {
        target += 1;
        __threadfence();                               // release data writes
        int g = b / NGRP;
        int old = atomicAdd(&g_gcnt[g][0], 1);
        if ((old % NGRP) == NGRP - 1) {                // group leader
            int rold = atomicAdd(&g_rcnt, 1);
            if ((rold % NGRP) == NGRP - 1) {           // root releaser
                __threadfence();
                st_rel(&g_rep, target);
            } else {
                while (ld_acq(&g_rep) < target) {}
            }
            st_rel(&g_gep[g][0], target);
        } else {
            while (ld_acq(&g_gep[g][0]) < target) {}
        }
        __threadfence();
    }
    __syncthreads();
}

// Message reconstruction at voxel i from z-blurred fields (L2 reads: data was
// produced by other SMs this launch). e^{-aI^2} prefactor cancels num/denom.
__device__ __forceinline__ void compute_msgs(
    int i, float Iv, float ws0, float ws1, float wb0, float wb1,
    float& m0, float& m1)
{
    const float ck[5] = {1.0f, 0.111111111f, 0.0061728395f,
                         2.28623686e-4f, 6.35066338e-6f};
    float p = 1.0f, nb = 0.f, b0 = 0.f, b1 = 0.f;
    #pragma unroll
    for (int k = 0; k < 5; ++k) {
        float cp = ck[k] * p;
        nb += cp * __ldcg(&g_nrm[k][i]);
        b0 += cp * __ldcg(&g_zb[2 * k + 0][i]);
        b1 += cp * __ldcg(&g_zb[2 * k + 1][i]);
        p *= Iv;
    }
    float inb = 1.0f / nb;
    float ins = 1.0f / __ldcg(&g_nrm[5][i]);
    m0 = __ldcg(&g_zb[10][i]) * ins * ws0 + b0 * inb * wb0;
    m1 = __ldcg(&g_zb[11][i]) * ins * ws1 + b1 * inb * wb1;
}

// ---------------------------------------------------------------------------
// One persistent kernel. Block b owns: phase1 slab z=b%24 for fields f0=b/24
// and f1=f0+6 (+ norm field f0 in iter 1); phase2 plane y=b%24 for the same
// fields. Both fields share class c = f0&1, so one compute_msgs per thread.
// Per iteration: phase1 (input build + x/y blur, 2 syncs) -> barrier ->
// phase2 (z blur via smem-staged planes, 1 sync) -> barrier.  10 barriers.
// ---------------------------------------------------------------------------
__global__ void __launch_bounds__(NT, 1)
crf_kernel(const float* __restrict__ u, const float* __restrict__ rgb,
           const float* __restrict__ ws, const float* __restrict__ wb,
           const float* __restrict__ Mc, float* __restrict__ out)
{
    __shared__ float kb24[576], ks24[576];   // bilateral (theta=160) / spatial (theta=3)
    __shared__ float kb16[256], ks16[256];
    __shared__ float Sin[3 * 384], Smid[3 * 384];

    const int b = blockIdx.x, t = threadIdx.x;
    int target = 0;
    if (t == 0) target = ld_acq(&g_rep);     // replay-safe epoch base

    for (int idx = t; idx < 576; idx += NT) {
        float d = (float)(idx / 24) - (float)(idx % 24), d2 = d * d;
        kb24[idx] = __expf(-d2 * (0.5f / 25600.f));
        ks24[idx] = __expf(-d2 * (0.5f / 9.f));
    }
    for (int idx = t; idx < 256; idx += NT) {
        float d = (float)(idx / 16) - (float)(idx % 16), d2 = d * d;
        kb16[idx] = __expf(-d2 * (0.5f / 25600.f));
        ks16[idx] = __expf(-d2 * (0.5f / 9.f));
    }
    // (first __syncthreads in phase1 orders kmat writes before reads)

    const float ws0 = ws[0], ws1 = ws[1], wb0 = wb[0], wb1 = wb[1];
    const float M00 = Mc[0], M01 = Mc[1], M10 = Mc[2], M11 = Mc[3];
    const float A = 1.0f / 18.0f;

    const int f0 = b / 24, zy = b % 24;      // slab (phase1) == plane (phase2)
    const int f1 = f0 + 6;
    const int c  = f0 & 1;                   // both fields share the class
    const bool bil1 = (f1 < 10);
    const int i  = zy * 384 + t;             // phase1 voxel
    const int yy = t >> 4, xx = t & 15;      // in-slab coords (yy is z in phase2)

    const float* k16u1 = bil1 ? kb16 : ks16;
    const float* k24u1 = bil1 ? kb24 : ks24;
    const float* k16un = (f0 < 5) ? kb16 : ks16;
    const float* k24un = (f0 < 5) ? kb24 : ks24;

    // Per-thread constants (fixed across iterations)
    const float Iv = rgb[i];
    const float eI = __expf(-A * Iv * Iv);
    float Ip[5]; Ip[0] = 1.f;
    #pragma unroll
    for (int k = 1; k < 5; ++k) Ip[k] = Ip[k - 1] * Iv;
    const float bf0 = eI * Ip[f0 >> 1];                    // unit0: always bilateral
    const float bf1 = bil1 ? eI * Ip[f1 >> 1] : 1.f;       // unit1
    const float bfn = (f0 < 5) ? eI * Ip[f0] : 1.f;        // norm unit (iter 1)
    const float u_c = u[2 * i + c];

    const int poff = (t >> 4) * 384 + zy * 16 + (t & 15);  // phase2 plane-load idx
    const int oi   = yy * 384 + zy * 16 + xx;              // phase2 output voxel

    for (int it = 1; it <= 5; ++it) {
        // ------------- phase 1: input build + x/y blur -------------
        float q;
        if (it == 1) {
            q = u_c;
        } else {
            float m0, m1;
            compute_msgs(i, Iv, ws0, ws1, wb0, wb1, m0, m1);
            float pw = (c == 0) ? (m0 * M00 + m1 * M01) : (m0 * M10 + m1 * M11);
            q = u_c - pw;
        }
        Sin[0 * 384 + t] = bf0 * q;
        Sin[1 * 384 + t] = bf1 * q;
        if (it == 1) Sin[2 * 384 + t] = bfn;
        __syncthreads();
        {   // x-pass (k broadcast over lanes; s broadcast within y-group)
            float a0 = 0.f, a1 = 0.f, a2 = 0.f;
            #pragma unroll
            for (int xp = 0; xp < 16; ++xp) {
                float s0 = Sin[0 * 384 + (yy << 4) + xp];
                float s1 = Sin[1 * 384 + (yy << 4) + xp];
                a0 += kb16 [xp * 16 + xx] * s0;
                a1 += k16u1[xp * 16 + xx] * s1;
            }
            if (it == 1) {
                #pragma unroll
                for (int xp = 0; xp < 16; ++xp)
                    a2 += k16un[xp * 16 + xx] * Sin[2 * 384 + (yy << 4) + xp];
            }
            Smid[0 * 384 + t] = a0;
            Smid[1 * 384 + t] = a1;
            if (it == 1) Smid[2 * 384 + t] = a2;
        }
        __syncthreads();
        {   // y-pass + global store
            float o0 = 0.f, o1 = 0.f, o2 = 0.f;
            #pragma unroll
            for (int yp = 0; yp < 24; ++yp) {
                float s0 = Smid[0 * 384 + (yp << 4) + xx];
                float s1 = Smid[1 * 384 + (yp << 4) + xx];
                o0 += kb24 [yp * 24 + yy] * s0;
                o1 += k24u1[yp * 24 + yy] * s1;
            }
            if (it == 1) {
                #pragma unroll
                for (int yp = 0; yp < 24; ++yp)
                    o2 += k24un[yp * 24 + yy] * Smid[2 * 384 + (yp << 4) + xx];
            }
            g_xy[f0][i] = o0;
            g_xy[f1][i] = o1;
            if (it == 1) g_xy[12 + f0][i] = o2;
        }
        gridbar(target, b);

        // ------------- phase 2: z blur (plane y = zy) -------------
        Sin[0 * 384 + t] = __ldcg(&g_xy[f0][poff]);
        Sin[1 * 384 + t] = __ldcg(&g_xy[f1][poff]);
        if (it == 1) Sin[2 * 384 + t] = __ldcg(&g_xy[12 + f0][poff]);
        __syncthreads();
        {
            float o0 = 0.f, o1 = 0.f, o2 = 0.f;
            #pragma unroll
            for (int zp = 0; zp < 24; ++zp) {
                float s0 = Sin[0 * 384 + (zp << 4) + xx];
                float s1 = Sin[1 * 384 + (zp << 4) + xx];
                o0 += kb24 [zp * 24 + yy] * s0;   // yy == output z
                o1 += k24u1[zp * 24 + yy] * s1;
            }
            if (it == 1) {
                #pragma unroll
                for (int zp = 0; zp < 24; ++zp)
                    o2 += k24un[zp * 24 + yy] * Sin[2 * 384 + (zp << 4) + xx];
            }
            g_zb[f0][oi] = o0;
            g_zb[f1][oi] = o1;
            if (it == 1) g_nrm[f0][oi] = o2;
        }
        gridbar(target, b);
    }

    // ------------- final combine: q5 = u - message @ compat^T -------------
    if (t < 64) {
        int ii = b * 64 + t;
        float m0, m1;
        compute_msgs(ii, rgb[ii], ws0, ws1, wb0, wb1, m0, m1);
        float2 o;
        o.x = u[2 * ii + 0] - (m0 * M00 + m1 * M01);
        o.y = u[2 * ii + 1] - (m0 * M10 + m1 * M11);
        reinterpret_cast<float2*>(out)[ii] = o;
    }
}

// ---------------------------------------------------------------------------
// Inputs (metadata order): unaries[18432] f32, rgb[9216] f32,
// spatial_ker_weights[2] f32, bilateral_ker_weights[2] f32,
// compatibility_matrix[4] f32 (row-major). Output: float32 [18432].
// ---------------------------------------------------------------------------
extern "C" void kernel_launch(void* const* d_in, const int* in_sizes, int n_in,
                              void* d_out, int out_size) {
    const float* u   = (const float*)d_in[0];
    const float* rgb = (const float*)d_in[1];
    const float* ws  = (const float*)d_in[2];
    const float* wb  = (const float*)d_in[3];
    const float* Mc  = (const float*)d_in[4];
    crf_kernel<<<NB, NT>>>(u, rgb, ws, wb, Mc, (float*)d_out);
}

// round 6
// speedup vs baseline: 1.0369x; 1.0369x over previous
#include <cuda_runtime.h>

// Geometry: (1, D=24, H=24, W=16, C=2); N = 9216 voxels.
#define NV   9216
#define NB   144     // blocks; <= 148 SMs so all co-resident (safe grid barrier)
#define NT   384
#define NGRP 12      // two-level barrier: 12 groups of 12 blocks

// Taylor rank-5 factorization of the bilateral intensity kernel:
//   exp(-(Ii-Ij)^2/18) = e^{-Ii^2/18} e^{-Ij^2/18} * sum_k c_k Ii^k Ij^k,
//   c_k = (1/9)^k / k!,  truncation error ~1.4e-7.
// Basis fields f = 2k+c (k=0..4, c=0..1); spatial fields f = 10+c.

__device__ float g_xy[18][NV];    // xy-blurred fields (12..17 = norm, iter 1 only)
__device__ float g_zb[12][NV];    // z-blurred basis fields
__device__ float g_nrm[6][NV];    // z-blurred norm fields (0..4 bilateral basis, 5 spatial)
__device__ int   g_gcnt[NGRP][64];  // group arrival counters (monotonic), 256B apart
__device__ int   g_gep [NGRP][64];  // group epochs
__device__ int   g_rcnt;            // root counter (monotonic)
__device__ int   g_rep;             // root epoch

__device__ __forceinline__ int ld_acq(const int* p) {
    int v; asm volatile("ld.global.acquire.gpu.b32 %0, [%1];" : "=r"(v) : "l"(p) : "memory");
    return v;
}
__device__ __forceinline__ void st_rel(int* p, int v) {
    asm volatile("st.global.release.gpu.b32 [%0], %1;" :: "l"(p), "r"(v) : "memory");
}

// Two-level grid barrier. Counters are monotonic (exactly NGRP increments per
// counter per barrier), so no resets are needed and state is replay-safe.
__device__ __forceinline__ void gridbar(int& target, int b) {
    __syncthreads();
    if (threadIdx.x == 0) {
        target += 1;
        __threadfence();                               // release data writes
        int g = b / NGRP;
        int old = atomicAdd(&g_gcnt[g][0], 1);
        if ((old % NGRP) == NGRP - 1) {                // group leader
            int rold = atomicAdd(&g_rcnt, 1);
            if ((rold % NGRP) == NGRP - 1) {           // root releaser
                __threadfence();
                st_rel(&g_rep, target);
            } else {
                while (ld_acq(&g_rep) < target) {}
            }
            st_rel(&g_gep[g][0], target);
        } else {
            while (ld_acq(&g_gep[g][0]) < target) {}
        }
        __threadfence();
    }
    __syncthreads();
}

// Message reconstruction at voxel i from z-blurred fields (L2 reads: data was
// produced by other SMs this launch). e^{-aI^2} prefactor cancels num/denom.
__device__ __forceinline__ void compute_msgs(
    int i, float Iv, float ws0, float ws1, float wb0, float wb1,
    float& m0, float& m1)
{
    const float ck[5] = {1.0f, 0.111111111f, 0.0061728395f,
                         2.28623686e-4f, 6.35066338e-6f};
    float p = 1.0f, nb = 0.f, b0 = 0.f, b1 = 0.f;
    #pragma unroll
    for (int k = 0; k < 5; ++k) {
        float cp = ck[k] * p;
        nb += cp * __ldcg(&g_nrm[k][i]);
        b0 += cp * __ldcg(&g_zb[2 * k + 0][i]);
        b1 += cp * __ldcg(&g_zb[2 * k + 1][i]);
        p *= Iv;
    }
    float inb = 1.0f / nb;
    float ins = 1.0f / __ldcg(&g_nrm[5][i]);
    m0 = __ldcg(&g_zb[10][i]) * ins * ws0 + b0 * inb * wb0;
    m1 = __ldcg(&g_zb[11][i]) * ins * ws1 + b1 * inb * wb1;
}

// ---------------------------------------------------------------------------
// One persistent kernel. Block b owns: phase1 slab z=b%24 for fields f0=b/24
// and f1=f0+6 (+ norm field f0 in iter 1); phase2 plane y=b%24 for the same
// fields. Both fields share class c = f0&1, so one compute_msgs per thread.
// Per iteration: phase1 (input build + x/y blur, 2 syncs) -> barrier ->
// phase2 (z blur via smem-staged planes, 1 sync) -> barrier.  10 barriers.
// ---------------------------------------------------------------------------
__global__ void __launch_bounds__(NT, 1)
crf_kernel(const float* __restrict__ u, const float* __restrict__ rgb,
           const float* __restrict__ ws, const float* __restrict__ wb,
           const float* __restrict__ Mc, float* __restrict__ out)
{
    __shared__ float kb24[576], ks24[576];   // bilateral (theta=160) / spatial (theta=3)
    __shared__ float kb16[256], ks16[256];
    __shared__ float Sin[3 * 384], Smid[3 * 384];

    const int b = blockIdx.x, t = threadIdx.x;
    int target = 0;
    if (t == 0) target = ld_acq(&g_rep);     // replay-safe epoch base

    for (int idx = t; idx < 576; idx += NT) {
        float d = (float)(idx / 24) - (float)(idx % 24), d2 = d * d;
        kb24[idx] = __expf(-d2 * (0.5f / 25600.f));
        ks24[idx] = __expf(-d2 * (0.5f / 9.f));
    }
    for (int idx = t; idx < 256; idx += NT) {
        float d = (float)(idx / 16) - (float)(idx % 16), d2 = d * d;
        kb16[idx] = __expf(-d2 * (0.5f / 25600.f));
        ks16[idx] = __expf(-d2 * (0.5f / 9.f));
    }
    // (first __syncthreads in phase1 orders kmat writes before reads)

    const float ws0 = ws[0], ws1 = ws[1], wb0 = wb[0], wb1 = wb[1];
    const float M00 = Mc[0], M01 = Mc[1], M10 = Mc[2], M11 = Mc[3];
    const float A = 1.0f / 18.0f;

    const int f0 = b / 24, zy = b % 24;      // slab (phase1) == plane (phase2)
    const int f1 = f0 + 6;
    const int c  = f0 & 1;                   // both fields share the class
    const bool bil1 = (f1 < 10);
    const int i  = zy * 384 + t;             // phase1 voxel
    const int yy = t >> 4, xx = t & 15;      // in-slab coords (yy is z in phase2)

    const float* k16u1 = bil1 ? kb16 : ks16;
    const float* k24u1 = bil1 ? kb24 : ks24;
    const float* k16un = (f0 < 5) ? kb16 : ks16;
    const float* k24un = (f0 < 5) ? kb24 : ks24;

    // Per-thread constants (fixed across iterations)
    const float Iv = rgb[i];
    const float eI = __expf(-A * Iv * Iv);
    float Ip[5]; Ip[0] = 1.f;
    #pragma unroll
    for (int k = 1; k < 5; ++k) Ip[k] = Ip[k - 1] * Iv;
    const float bf0 = eI * Ip[f0 >> 1];                    // unit0: always bilateral
    const float bf1 = bil1 ? eI * Ip[f1 >> 1] : 1.f;       // unit1
    const float bfn = (f0 < 5) ? eI * Ip[f0] : 1.f;        // norm unit (iter 1)
    const float u_c = u[2 * i + c];

    const int poff = (t >> 4) * 384 + zy * 16 + (t & 15);  // phase2 plane-load idx
    const int oi   = yy * 384 + zy * 16 + xx;              // phase2 output voxel

    for (int it = 1; it <= 5; ++it) {
        // ------------- phase 1: input build + x/y blur -------------
        float q;
        if (it == 1) {
            q = u_c;
        } else {
            float m0, m1;
            compute_msgs(i, Iv, ws0, ws1, wb0, wb1, m0, m1);
            float pw = (c == 0) ? (m0 * M00 + m1 * M01) : (m0 * M10 + m1 * M11);
            q = u_c - pw;
        }
        Sin[0 * 384 + t] = bf0 * q;
        Sin[1 * 384 + t] = bf1 * q;
        if (it == 1) Sin[2 * 384 + t] = bfn;
        __syncthreads();
        {   // x-pass (k broadcast over lanes; s broadcast within y-group)
            float a0 = 0.f, a1 = 0.f, a2 = 0.f;
            #pragma unroll
            for (int xp = 0; xp < 16; ++xp) {
                float s0 = Sin[0 * 384 + (yy << 4) + xp];
                float s1 = Sin[1 * 384 + (yy << 4) + xp];
                a0 += kb16 [xp * 16 + xx] * s0;
                a1 += k16u1[xp * 16 + xx] * s1;
            }
            if (it == 1) {
                #pragma unroll
                for (int xp = 0; xp < 16; ++xp)
                    a2 += k16un[xp * 16 + xx] * Sin[2 * 384 + (yy << 4) + xp];
            }
            Smid[0 * 384 + t] = a0;
            Smid[1 * 384 + t] = a1;
            if (it == 1) Smid[2 * 384 + t] = a2;
        }
        __syncthreads();
        {   // y-pass + global store
            float o0 = 0.f, o1 = 0.f, o2 = 0.f;
            #pragma unroll
            for (int yp = 0; yp < 24; ++yp) {
                float s0 = Smid[0 * 384 + (yp << 4) + xx];
                float s1 = Smid[1 * 384 + (yp << 4) + xx];
                o0 += kb24 [yp * 24 + yy] * s0;
                o1 += k24u1[yp * 24 + yy] * s1;
            }
            if (it == 1) {
                #pragma unroll
                for (int yp = 0; yp < 24; ++yp)
                    o2 += k24un[yp * 24 + yy] * Smid[2 * 384 + (yp << 4) + xx];
            }
            g_xy[f0][i] = o0;
            g_xy[f1][i] = o1;
            if (it == 1) g_xy[12 + f0][i] = o2;
        }
        gridbar(target, b);

        // ------------- phase 2: z blur (plane y = zy) -------------
        Sin[0 * 384 + t] = __ldcg(&g_xy[f0][poff]);
        Sin[1 * 384 + t] = __ldcg(&g_xy[f1][poff]);
        if (it == 1) Sin[2 * 384 + t] = __ldcg(&g_xy[12 + f0][poff]);
        __syncthreads();
        {
            float o0 = 0.f, o1 = 0.f, o2 = 0.f;
            #pragma unroll
            for (int zp = 0; zp < 24; ++zp) {
                float s0 = Sin[0 * 384 + (zp << 4) + xx];
                float s1 = Sin[1 * 384 + (zp << 4) + xx];
                o0 += kb24 [zp * 24 + yy] * s0;   // yy == output z
                o1 += k24u1[zp * 24 + yy] * s1;
            }
            if (it == 1) {
                #pragma unroll
                for (int zp = 0; zp < 24; ++zp)
                    o2 += k24un[zp * 24 + yy] * Sin[2 * 384 + (zp << 4) + xx];
            }
            g_zb[f0][oi] = o0;
            g_zb[f1][oi] = o1;
            if (it == 1) g_nrm[f0][oi] = o2;
        }
        gridbar(target, b);
    }

    // ------------- final combine: q5 = u - message @ compat^T -------------
    if (t < 64) {
        int ii = b * 64 + t;
        float m0, m1;
        compute_msgs(ii, rgb[ii], ws0, ws1, wb0, wb1, m0, m1);
        float2 o;
        o.x = u[2 * ii + 0] - (m0 * M00 + m1 * M01);
        o.y = u[2 * ii + 1] - (m0 * M10 + m1 * M11);
        reinterpret_cast<float2*>(out)[ii] = o;
    }
}

// ---------------------------------------------------------------------------
// Inputs (metadata order): unaries[18432] f32, rgb[9216] f32,
// spatial_ker_weights[2] f32, bilateral_ker_weights[2] f32,
// compatibility_matrix[4] f32 (row-major). Output: float32 [18432].
// ---------------------------------------------------------------------------
extern "C" void kernel_launch(void* const* d_in, const int* in_sizes, int n_in,
                              void* d_out, int out_size) {
    const float* u   = (const float*)d_in[0];
    const float* rgb = (const float*)d_in[1];
    const float* ws  = (const float*)d_in[2];
    const float* wb  = (const float*)d_in[3];
    const float* Mc  = (const float*)d_in[4];
    crf_kernel<<<NB, NT>>>(u, rgb, ws, wb, Mc, (float*)d_out);
}

// round 7
// speedup vs baseline: 1.5126x; 1.4587x over previous
#include <cuda_runtime.h>

// Geometry: (1, D=24, H=24, W=16, C=2); N = 9216 voxels.
#define NV   9216
#define NB   144     // blocks; <= 148 SMs so all co-resident (safe grid barrier)
#define NT   384

// Taylor rank-5 factorization of the bilateral intensity kernel:
//   exp(-(Ii-Ij)^2/18) = e^{-Ii^2/18} e^{-Ij^2/18} * sum_k c_k Ii^k Ij^k,
//   c_k = (1/9)^k / k!,  truncation error ~1.4e-7.
// Basis fields f = 2k+c (k=0..4, c=0..1); spatial fields f = 10+c.

__device__ float g_xy[18][NV];    // xy-blurred fields (12..17 = norm, iter 1 only)
__device__ float g_zb[12][NV];    // z-blurred basis fields
__device__ float g_nrm[6][NV];    // z-blurred norm fields (0..4 bilateral, 5 spatial)
__device__ int   g_flags[NB][32]; // per-block monotonic arrival counters, 128B apart

__device__ __forceinline__ int ld_acq(const int* p) {
    int v; asm volatile("ld.global.acquire.gpu.b32 %0, [%1];" : "=r"(v) : "l"(p) : "memory");
    return v;
}
__device__ __forceinline__ void st_rel(int* p, int v) {
    asm volatile("st.global.release.gpu.b32 [%0], %1;" :: "l"(p), "r"(v) : "memory");
}

// Flat flag-array grid barrier: parallel arrivals (144 distinct L2 lines),
// direct all-to-all detection (no leader hops). Counters are monotonic, so
// no resets are needed and state is consistent across CUDA-graph replays.
// Visibility: st.release (arrival) -> ld.acquire (poll) is a gpu-scope
// release/acquire pair; __syncthreads/bar.red extend it across the CTA.
__device__ __forceinline__ void gridbar(int& target) {
    __syncthreads();                   // all block's data writes done
    target += 1;
    if (threadIdx.x == 0)
        st_rel(&g_flags[blockIdx.x][0], target);
    const int t = threadIdx.x;
    int v;
    do {
        v = (t < NB) ? ld_acq(&g_flags[t][0]) : target;
    } while (__syncthreads_count(v >= target) < NT);
}

// Message reconstruction at voxel i from z-blurred fields (L2 reads: data was
// produced by other SMs this launch). e^{-aI^2} prefactor cancels num/denom.
__device__ __forceinline__ void compute_msgs(
    int i, float Iv, float ws0, float ws1, float wb0, float wb1,
    float& m0, float& m1)
{
    const float ck[5] = {1.0f, 0.111111111f, 0.0061728395f,
                         2.28623686e-4f, 6.35066338e-6f};
    float p = 1.0f, nb = 0.f, b0 = 0.f, b1 = 0.f;
    #pragma unroll
    for (int k = 0; k < 5; ++k) {
        float cp = ck[k] * p;
        nb += cp * __ldcg(&g_nrm[k][i]);
        b0 += cp * __ldcg(&g_zb[2 * k + 0][i]);
        b1 += cp * __ldcg(&g_zb[2 * k + 1][i]);
        p *= Iv;
    }
    float inb = 1.0f / nb;
    float ins = 1.0f / __ldcg(&g_nrm[5][i]);
    m0 = __ldcg(&g_zb[10][i]) * ins * ws0 + b0 * inb * wb0;
    m1 = __ldcg(&g_zb[11][i]) * ins * ws1 + b1 * inb * wb1;
}

// ---------------------------------------------------------------------------
// One persistent kernel. Block b owns: phase1 slab z=b%24 for fields f0=b/24
// and f1=f0+6 (+ norm field f0 in iter 1); phase2 plane y=b%24 for the same
// fields. Both fields share class c = f0&1, so one compute_msgs per thread.
// Per iteration: phase1 (input build + x/y blur) -> barrier ->
// phase2 (z blur via smem-staged planes) -> barrier.  10 barriers total.
// ---------------------------------------------------------------------------
__global__ void __launch_bounds__(NT, 1)
crf_kernel(const float* __restrict__ u, const float* __restrict__ rgb,
           const float* __restrict__ ws, const float* __restrict__ wb,
           const float* __restrict__ Mc, float* __restrict__ out)
{
    __shared__ float kb24[576], ks24[576];   // bilateral (theta=160) / spatial (theta=3)
    __shared__ float kb16[256], ks16[256];
    __shared__ float Sin[3 * 384], Smid[3 * 384];

    const int b = blockIdx.x, t = threadIdx.x;
    // Replay-safe epoch base: this block's own flag (its last written value).
    int target = ld_acq(&g_flags[b][0]);

    for (int idx = t; idx < 576; idx += NT) {
        float d = (float)(idx / 24) - (float)(idx % 24), d2 = d * d;
        kb24[idx] = __expf(-d2 * (0.5f / 25600.f));
        ks24[idx] = __expf(-d2 * (0.5f / 9.f));
    }
    for (int idx = t; idx < 256; idx += NT) {
        float d = (float)(idx / 16) - (float)(idx % 16), d2 = d * d;
        kb16[idx] = __expf(-d2 * (0.5f / 25600.f));
        ks16[idx] = __expf(-d2 * (0.5f / 9.f));
    }
    // (first __syncthreads in phase1 orders kmat writes before reads)

    const float ws0 = ws[0], ws1 = ws[1], wb0 = wb[0], wb1 = wb[1];
    const float M00 = Mc[0], M01 = Mc[1], M10 = Mc[2], M11 = Mc[3];
    const float A = 1.0f / 18.0f;

    const int f0 = b / 24, zy = b % 24;      // slab (phase1) == plane (phase2)
    const int f1 = f0 + 6;
    const int c  = f0 & 1;                   // both fields share the class
    const bool bil1 = (f1 < 10);
    const int i  = zy * 384 + t;             // phase1 voxel
    const int yy = t >> 4, xx = t & 15;      // in-slab coords (yy is z in phase2)

    const float* k16u1 = bil1 ? kb16 : ks16;
    const float* k24u1 = bil1 ? kb24 : ks24;
    const float* k16un = (f0 < 5) ? kb16 : ks16;
    const float* k24un = (f0 < 5) ? kb24 : ks24;

    // Per-thread constants (fixed across iterations)
    const float Iv = rgb[i];
    const float eI = __expf(-A * Iv * Iv);
    float Ip[5]; Ip[0] = 1.f;
    #pragma unroll
    for (int k = 1; k < 5; ++k) Ip[k] = Ip[k - 1] * Iv;
    const float bf0 = eI * Ip[f0 >> 1];                    // unit0: always bilateral
    const float bf1 = bil1 ? eI * Ip[f1 >> 1] : 1.f;       // unit1
    const float bfn = (f0 < 5) ? eI * Ip[f0] : 1.f;        // norm unit (iter 1)
    const float u_c = u[2 * i + c];

    const int poff = (t >> 4) * 384 + zy * 16 + (t & 15);  // phase2 plane-load idx
    const int oi   = yy * 384 + zy * 16 + xx;              // phase2 output voxel

    for (int it = 1; it <= 5; ++it) {
        // ------------- phase 1: input build + x/y blur -------------
        float q;
        if (it == 1) {
            q = u_c;
        } else {
            float m0, m1;
            compute_msgs(i, Iv, ws0, ws1, wb0, wb1, m0, m1);
            float pw = (c == 0) ? (m0 * M00 + m1 * M01) : (m0 * M10 + m1 * M11);
            q = u_c - pw;
        }
        Sin[0 * 384 + t] = bf0 * q;
        Sin[1 * 384 + t] = bf1 * q;
        if (it == 1) Sin[2 * 384 + t] = bfn;
        __syncthreads();
        {   // x-pass (k broadcast within warp; s broadcast within y-group)
            float a0 = 0.f, a1 = 0.f, a2 = 0.f;
            #pragma unroll
            for (int xp = 0; xp < 16; ++xp) {
                float s0 = Sin[0 * 384 + (yy << 4) + xp];
                float s1 = Sin[1 * 384 + (yy << 4) + xp];
                a0 += kb16 [xp * 16 + xx] * s0;
                a1 += k16u1[xp * 16 + xx] * s1;
            }
            if (it == 1) {
                #pragma unroll
                for (int xp = 0; xp < 16; ++xp)
                    a2 += k16un[xp * 16 + xx] * Sin[2 * 384 + (yy << 4) + xp];
            }
            Smid[0 * 384 + t] = a0;
            Smid[1 * 384 + t] = a1;
            if (it == 1) Smid[2 * 384 + t] = a2;
        }
        __syncthreads();
        {   // y-pass + global store
            float o0 = 0.f, o1 = 0.f, o2 = 0.f;
            #pragma unroll
            for (int yp = 0; yp < 24; ++yp) {
                float s0 = Smid[0 * 384 + (yp << 4) + xx];
                float s1 = Smid[1 * 384 + (yp << 4) + xx];
                o0 += kb24 [yp * 24 + yy] * s0;
                o1 += k24u1[yp * 24 + yy] * s1;
            }
            if (it == 1) {
                #pragma unroll
                for (int yp = 0; yp < 24; ++yp)
                    o2 += k24un[yp * 24 + yy] * Smid[2 * 384 + (yp << 4) + xx];
            }
            g_xy[f0][i] = o0;
            g_xy[f1][i] = o1;
            if (it == 1) g_xy[12 + f0][i] = o2;
        }
        gridbar(target);

        // ------------- phase 2: z blur (plane y = zy) -------------
        Sin[0 * 384 + t] = __ldcg(&g_xy[f0][poff]);
        Sin[1 * 384 + t] = __ldcg(&g_xy[f1][poff]);
        if (it == 1) Sin[2 * 384 + t] = __ldcg(&g_xy[12 + f0][poff]);
        __syncthreads();
        {
            float o0 = 0.f, o1 = 0.f, o2 = 0.f;
            #pragma unroll
            for (int zp = 0; zp < 24; ++zp) {
                float s0 = Sin[0 * 384 + (zp << 4) + xx];
                float s1 = Sin[1 * 384 + (zp << 4) + xx];
                o0 += kb24 [zp * 24 + yy] * s0;   // yy == output z
                o1 += k24u1[zp * 24 + yy] * s1;
            }
            if (it == 1) {
                #pragma unroll
                for (int zp = 0; zp < 24; ++zp)
                    o2 += k24un[zp * 24 + yy] * Sin[2 * 384 + (zp << 4) + xx];
            }
            g_zb[f0][oi] = o0;
            g_zb[f1][oi] = o1;
            if (it == 1) g_nrm[f0][oi] = o2;
        }
        gridbar(target);
    }

    // ------------- final combine: q5 = u - message @ compat^T -------------
    if (t < 64) {
        int ii = b * 64 + t;
        float m0, m1;
        compute_msgs(ii, rgb[ii], ws0, ws1, wb0, wb1, m0, m1);
        float2 o;
        o.x = u[2 * ii + 0] - (m0 * M00 + m1 * M01);
        o.y = u[2 * ii + 1] - (m0 * M10 + m1 * M11);
        reinterpret_cast<float2*>(out)[ii] = o;
    }
}

// ---------------------------------------------------------------------------
// Inputs (metadata order): unaries[18432] f32, rgb[9216] f32,
// spatial_ker_weights[2] f32, bilateral_ker_weights[2] f32,
// compatibility_matrix[4] f32 (row-major). Output: float32 [18432].
// ---------------------------------------------------------------------------
extern "C" void kernel_launch(void* const* d_in, const int* in_sizes, int n_in,
                              void* d_out, int out_size) {
    const float* u   = (const float*)d_in[0];
    const float* rgb = (const float*)d_in[1];
    const float* ws  = (const float*)d_in[2];
    const float* wb  = (const float*)d_in[3];
    const float* Mc  = (const float*)d_in[4];
    crf_kernel<<<NB, NT>>>(u, rgb, ws, wb, Mc, (float*)d_out);
}